// round 16
// baseline (speedup 1.0000x reference)
#include <cuda_runtime.h>
#include <cuda_fp16.h>
#include <cstdint>

// Problem constants
#define BATCH 2
#define NA 256
#define NB 256
#define EDIM 512
#define H1 300
#define H2 100
#define HP 304   // fp16 row pitch for h matrices (38 uint4 per row)

// ---------------- scratch (device globals; no allocation) ----------------
__device__ __half g_hAa[BATCH * NA * HP];
__device__ __half g_hAb[BATCH * NA * HP];
__device__ __half g_hBa[BATCH * NB * HP];
__device__ __half g_hBb[BATCH * NB * HP];
__device__ float g_R2[BATCH * NA * NB];
__device__ float g_geo[BATCH * 16];
__device__ float g_y1[BATCH * 64 * NA];
__device__ __half g_Wimg[304 * 104];   // W2 fp16 image, pitch 208 B, zero padded

// ---------------- helpers (baseline PTX only) ----------------------------
__device__ __forceinline__ uint32_t smem_u32(const void* p) {
    uint32_t a;
    asm("{ .reg .u64 t; cvta.to.shared.u64 t, %1; cvt.u32.u64 %0, t; }" : "=r"(a) : "l"(p));
    return a;
}
__device__ __forceinline__ void ldsm_x2t(uint32_t addr, uint32_t& r0, uint32_t& r1) {
    asm volatile("ldmatrix.sync.aligned.m8n8.x2.trans.shared.b16 {%0,%1}, [%2];"
                 : "=r"(r0), "=r"(r1) : "r"(addr));
}
__device__ __forceinline__ void mma16816(float* c, const uint32_t* a, uint32_t b0, uint32_t b1) {
    asm volatile("mma.sync.aligned.m16n8k16.row.col.f32.f16.f16.f32 "
                 "{%0,%1,%2,%3}, {%4,%5,%6,%7}, {%8,%9}, {%0,%1,%2,%3};"
                 : "+f"(c[0]), "+f"(c[1]), "+f"(c[2]), "+f"(c[3])
                 : "r"(a[0]), "r"(a[1]), "r"(a[2]), "r"(a[3]), "r"(b0), "r"(b1));
}

// smem layout for k2 (byte offsets; all 16B aligned)
#define WPITCH   208           // 104 fp16 cols per k-row (conflict-free ldsm)
#define SPITCH_H 328           // stage pitch in halves (656 B)
#define SM_W     0             // 304*208 = 63232
#define SM_S     63232         // 48*656 = 31488 -> 94720
#define SM_B2    94720         // 128 floats -> 95232
#define SM_W3    95232         // 128 floats -> 95744
#define SM_VP    95744         // 3*256 floats = 3072 -> 98816
#define SM_TOTAL 98816

#define KSTEPS   19            // ceil(300/16) -> 304 = HP exactly

// =========================================================================
// KP: fused prep. Blocks 0..149: W2 -> fp16 image [304][104]. Blocks
// 150..157: pointnet layer0 GEMM. Blocks 158..159: per-batch geometry.
// =========================================================================
__global__ void kp_prep(const float* __restrict__ W2,
                        const float* __restrict__ actE, const float* __restrict__ W0,
                        const float* __restrict__ b0, const float* __restrict__ anch) {
    if (blockIdx.x < 150) {
        int idx = blockIdx.x * 256 + threadIdx.x;
        if (idx >= 304 * 104) return;
        int k = idx / 104, n = idx % 104;
        float w = (k < H1 && n < H2) ? W2[k * H2 + n] : 0.f;
        g_Wimg[idx] = __float2half(w);
        return;
    }
    if (blockIdx.x < 158) {
        int bl = blockIdx.x - 150;
        int bi = bl >> 2;
        int n0 = (bl & 3) * 64;
        const float* x = actE + bi * EDIM * NA;
        int tid = threadIdx.x;
        int tx = tid & 15, ty = tid >> 4;
        __shared__ float As[16][64];
        __shared__ float Bs[16][64];
        float acc[4][4];
#pragma unroll
        for (int i = 0; i < 4; ++i)
#pragma unroll
            for (int j = 0; j < 4; ++j) acc[i][j] = 0.f;
        int o_l = tid & 63;
        int k4 = (tid >> 6) * 4;
        int lkk = tid / 16, l4 = (tid % 16) * 4;
        for (int k0 = 0; k0 < EDIM; k0 += 16) {
            __syncthreads();
            float4 w = *(const float4*)&W0[o_l * EDIM + k0 + k4];
            As[k4 + 0][o_l] = w.x; As[k4 + 1][o_l] = w.y;
            As[k4 + 2][o_l] = w.z; As[k4 + 3][o_l] = w.w;
            *(float4*)&Bs[lkk][l4] = *(const float4*)&x[(k0 + lkk) * NA + n0 + l4];
            __syncthreads();
#pragma unroll
            for (int kk = 0; kk < 16; ++kk) {
                float av[4], bv[4];
#pragma unroll
                for (int i = 0; i < 4; ++i) av[i] = As[kk][ty * 4 + i];
#pragma unroll
                for (int j = 0; j < 4; ++j) bv[j] = Bs[kk][tx * 4 + j];
#pragma unroll
                for (int i = 0; i < 4; ++i)
#pragma unroll
                    for (int j = 0; j < 4; ++j) acc[i][j] = fmaf(av[i], bv[j], acc[i][j]);
            }
        }
#pragma unroll
        for (int i = 0; i < 4; ++i) {
            int o = ty * 4 + i;
            float bb = b0[o];
#pragma unroll
            for (int j = 0; j < 4; ++j) {
                int n = n0 + tx * 4 + j;
                g_y1[(bi * 64 + o) * NA + n] = fmaxf(acc[i][j] + bb, 0.f);
            }
        }
        return;
    }
    // ---- geometry ----
    {
        int bi = blockIdx.x - 158, t = threadIdx.x;
        __shared__ float buf[9 * 256];
        __shared__ float q[3];
        const float* ap = anch + bi * 3 * NB;
        float px = ap[t], py = ap[NB + t], pz = ap[2 * NB + t];
        buf[t] = px; buf[256 + t] = py; buf[512 + t] = pz;
        __syncthreads();
        for (int s = 128; s; s >>= 1) {
            if (t < s)
                for (int cc = 0; cc < 3; ++cc) buf[cc * 256 + t] += buf[cc * 256 + t + s];
            __syncthreads();
        }
        if (t == 0) { q[0] = buf[0] / NB; q[1] = buf[256] / NB; q[2] = buf[512] / NB; }
        __syncthreads();
        float ax = 2.f * (px - q[0]), ay = 2.f * (py - q[1]), az = 2.f * (pz - q[2]);
        float cv = px * px + py * py + pz * pz;
        buf[t] = ax * ax;          buf[256 + t] = ax * ay;   buf[512 + t] = ax * az;
        buf[768 + t] = ay * ay;    buf[1024 + t] = ay * az;  buf[1280 + t] = az * az;
        buf[1536 + t] = ax * cv;   buf[1792 + t] = ay * cv;  buf[2048 + t] = az * cv;
        __syncthreads();
        for (int s = 128; s; s >>= 1) {
            if (t < s)
                for (int cc = 0; cc < 9; ++cc) buf[cc * 256 + t] += buf[cc * 256 + t + s];
            __syncthreads();
        }
        if (t == 0) {
            float m00 = buf[0], m01 = buf[256], m02 = buf[512];
            float m11 = buf[768], m12 = buf[1024], m22 = buf[1280];
            float det = m00 * (m11 * m22 - m12 * m12) - m01 * (m01 * m22 - m12 * m02)
                      + m02 * (m01 * m12 - m11 * m02);
            float inv = 1.f / det;
            float* geo = g_geo + bi * 16;
            geo[0] = (m11 * m22 - m12 * m12) * inv;
            geo[1] = (m02 * m12 - m01 * m22) * inv;
            geo[2] = (m01 * m12 - m02 * m11) * inv;
            geo[3] = (m00 * m22 - m02 * m02) * inv;
            geo[4] = (m02 * m01 - m00 * m12) * inv;
            geo[5] = (m00 * m11 - m01 * m01) * inv;
            geo[6] = buf[1536]; geo[7] = buf[1792]; geo[8] = buf[2048];
            geo[9] = q[0]; geo[10] = q[1]; geo[11] = q[2];
        }
    }
}

// =========================================================================
// K1: h matrices (fp32 SIMT GEMM) -> fp16 output, pitch 304, zero pad.
// =========================================================================
__global__ void k1_h(const float* __restrict__ actE, const float* __restrict__ anchE,
                     const float* __restrict__ W1, const float* __restrict__ b1) {
    int bi   = blockIdx.z & 1;
    int src  = (blockIdx.z >> 1) & 1;
    int half = blockIdx.z >> 2;
    const float* emb = (src ? anchE : actE) + bi * EDIM * NA;
    __half* outp = (half == 0 ? (src ? g_hBa : g_hAa) : (src ? g_hBb : g_hAb)) + bi * NA * HP;

    int n0 = blockIdx.y * 64;
    int j0 = blockIdx.x * 64;
    int tx = threadIdx.x, ty = threadIdx.y;
    int tid = ty * 16 + tx;

    __shared__ float As[16 * 64];
    __shared__ float Bs[16 * 64];

    float acc[4][4];
#pragma unroll
    for (int i = 0; i < 4; ++i)
#pragma unroll
        for (int j = 0; j < 4; ++j) acc[i][j] = 0.f;

    int wbase = half * 512;
    int lkk = tid / 16;
    int l4  = (tid % 16) * 4;

    for (int k0 = 0; k0 < EDIM; k0 += 16) {
        __syncthreads();
        *(float4*)&As[lkk * 64 + l4] = *(const float4*)&emb[(k0 + lkk) * NA + n0 + l4];
        {
            int jg = j0 + l4;
            float4 bv = make_float4(0.f, 0.f, 0.f, 0.f);
            if (jg < H1) bv = *(const float4*)&W1[(wbase + k0 + lkk) * H1 + jg];
            *(float4*)&Bs[lkk * 64 + l4] = bv;
        }
        __syncthreads();
#pragma unroll
        for (int kk = 0; kk < 16; ++kk) {
            float4 a4 = *(const float4*)&As[kk * 64 + ty * 4];
            float4 b4 = *(const float4*)&Bs[kk * 64 + tx * 4];
            float av[4] = {a4.x, a4.y, a4.z, a4.w};
            float bv[4] = {b4.x, b4.y, b4.z, b4.w};
#pragma unroll
            for (int i = 0; i < 4; ++i)
#pragma unroll
                for (int j = 0; j < 4; ++j) acc[i][j] = fmaf(av[i], bv[j], acc[i][j]);
        }
    }
#pragma unroll
    for (int i = 0; i < 4; ++i) {
        int n = n0 + ty * 4 + i;
#pragma unroll
        for (int j = 0; j < 4; ++j) {
            int jg = j0 + tx * 4 + j;
            if (jg < H1) {
                float v = acc[i][j];
                if (half == 0) v += b1[jg];
                outp[n * HP + jg] = __float2half(v);
            } else if (jg < HP) {
                outp[n * HP + jg] = __float2half(0.f);
            }
        }
    }
}

// =========================================================================
// K2: PERSISTENT pair-MLP tensor GEMM + pointnet-tail piggyback blocks.
// Blocks 0..147: GEMM (768 thr, 19 ks, 13 n-tiles 5/4/4).
// Blocks 148..211: pointnet tail (runs in k2's retire tail; needs only g_y1).
// =========================================================================
__device__ __forceinline__ uint4 stage_ld(int idx, int bi, int a0, int b0) {
    int row = idx / 41, i = idx % 41;
    if (i >= 38) return make_uint4(0u, 0u, 0u, 0u);
    const uint4* srcp;
    int gr;
    if (row < 16)      { srcp = (const uint4*)g_hAa; gr = bi * NA + a0 + row; }
    else if (row < 32) { srcp = (const uint4*)g_hAb; gr = bi * NA + a0 + row - 16; }
    else if (row < 40) { srcp = (const uint4*)g_hBb; gr = bi * NB + b0 + row - 32; }
    else               { srcp = (const uint4*)g_hBa; gr = bi * NB + b0 + row - 40; }
    return srcp[gr * 38 + i];
}

template <int NT>
__device__ __forceinline__ void k2_mainloop(float acc[2][5][4], const __half2* S2,
                                            uint32_t sbase, int srowB, int sa_row0,
                                            int jt0, int blane, int c0) {
    const __half2 z2 = __float2half2_rn(0.f);
#pragma unroll 1
    for (int ks = 0; ks < KSTEPS; ++ks) {
        const int kc = ks * 16 + c0;
        __half2 Blo = S2[(srowB * SPITCH_H + kc) >> 1];
        __half2 Bhi = S2[(srowB * SPITCH_H + kc + 8) >> 1];
        uint32_t afrag[2][4];
#pragma unroll
        for (int mt = 0; mt < 2; ++mt)
#pragma unroll
            for (int hf = 0; hf < 2; ++hf) {
                int srow = sa_row0 + mt * 2 + hf;
                __half2 Alo = S2[(srow * SPITCH_H + kc) >> 1];
                __half2 Ahi = S2[(srow * SPITCH_H + kc + 8) >> 1];
                __half2 x0 = __hmax2(__hadd2(Alo, Blo), z2);
                __half2 x1 = __hmax2(__hadd2(Ahi, Bhi), z2);
                afrag[mt][hf] = *(uint32_t*)&x0;
                afrag[mt][hf + 2] = *(uint32_t*)&x1;
            }
        const uint32_t wa = sbase + SM_W + (uint32_t)(ks * 16 + blane) * WPITCH
                          + (uint32_t)jt0 * 16;
#pragma unroll
        for (int nt = 0; nt < NT; ++nt) {
            uint32_t br0, br1;
            ldsm_x2t(wa + nt * 16, br0, br1);
            mma16816(acc[0][nt], afrag[0], br0, br1);
            mma16816(acc[1][nt], afrag[1], br0, br1);
        }
    }
}

__device__ __forceinline__ void layer_oi(const float* __restrict__ Wrow,
                                         const float* __restrict__ ys, int K,
                                         float* acc) {
#pragma unroll 4
    for (int i = 0; i < K; i += 4) {
        float4 w = *(const float4*)(Wrow + i);
#pragma unroll
        for (int u = 0; u < 4; ++u) {
            float wv = (&w.x)[u];
            const float* y = ys + (i + u) * 8;
            float4 p = *(const float4*)y;
            float4 q = *(const float4*)(y + 4);
            acc[0] = fmaf(wv, p.x, acc[0]); acc[1] = fmaf(wv, p.y, acc[1]);
            acc[2] = fmaf(wv, p.z, acc[2]); acc[3] = fmaf(wv, p.w, acc[3]);
            acc[4] = fmaf(wv, q.x, acc[4]); acc[5] = fmaf(wv, q.y, acc[5]);
            acc[6] = fmaf(wv, q.z, acc[6]); acc[7] = fmaf(wv, q.w, acc[7]);
        }
    }
}

__global__ void __launch_bounds__(768, 1) k2_hmma(
        const float* __restrict__ b2, const float* __restrict__ W3m,
        const float* __restrict__ b3p,
        const float* __restrict__ pW1, const float* __restrict__ pb1,
        const float* __restrict__ pW2, const float* __restrict__ pb2,
        const float* __restrict__ pW3, const float* __restrict__ pb3,
        const float* __restrict__ pW4, const float* __restrict__ pb4,
        const float* __restrict__ hW, float* __restrict__ out) {
    extern __shared__ char smem[];
    const int tid = threadIdx.x;

    // ================= pointnet-tail piggyback blocks =====================
    if (blockIdx.x >= 148) {
        int bl = blockIdx.x - 148;            // 0..63
        int bi = bl >> 5, n0 = (bl & 31) * 8;
        float* ya = (float*)(smem);            // 2048 B
        float* yb = (float*)(smem + 2048);     // 2048 B
        float* yc = (float*)(smem + 4096);     // 4096 B
        float* red2 = (float*)(smem + 8192);   // 512 B

        if (tid < 512)
            ya[tid] = g_y1[(bi * 64 + (tid >> 3)) * NA + n0 + (tid & 7)];
        __syncthreads();
        if (tid < 64) {
            float acc[8];
            float bb = pb1[tid];
#pragma unroll
            for (int nn = 0; nn < 8; ++nn) acc[nn] = bb;
            layer_oi(&pW1[tid * 64], ya, 64, acc);
#pragma unroll
            for (int nn = 0; nn < 8; ++nn) yb[tid * 8 + nn] = fmaxf(acc[nn], 0.f);
        }
        __syncthreads();
        if (tid < 64) {
            float acc[8];
            float bb = pb2[tid];
#pragma unroll
            for (int nn = 0; nn < 8; ++nn) acc[nn] = bb;
            layer_oi(&pW2[tid * 64], yb, 64, acc);
#pragma unroll
            for (int nn = 0; nn < 8; ++nn) ya[tid * 8 + nn] = fmaxf(acc[nn], 0.f);
        }
        __syncthreads();
        if (tid < 128) {
            float acc[8];
            float bb = pb3[tid];
#pragma unroll
            for (int nn = 0; nn < 8; ++nn) acc[nn] = bb;
            layer_oi(&pW3[tid * 64], ya, 64, acc);
#pragma unroll
            for (int nn = 0; nn < 8; ++nn) yc[tid * 8 + nn] = fmaxf(acc[nn], 0.f);
        }
        __syncthreads();
        if (tid < 512) {
            float acc[8];
            float bb = pb4[tid];
#pragma unroll
            for (int nn = 0; nn < 8; ++nn) acc[nn] = bb;
            layer_oi(&pW4[tid * 128], yc, 128, acc);
            float hw = hW[tid];
            float val[8];
#pragma unroll
            for (int nn = 0; nn < 8; ++nn) val[nn] = hw * fmaxf(acc[nn], 0.f);
#pragma unroll
            for (int nn = 0; nn < 8; ++nn) {
#pragma unroll
                for (int off = 16; off; off >>= 1)
                    val[nn] += __shfl_xor_sync(0xffffffffu, val[nn], off);
            }
            if ((tid & 31) == 0) {
                int w = tid >> 5;   // 0..15
#pragma unroll
                for (int nn = 0; nn < 8; ++nn) red2[nn * 16 + w] = val[nn];
            }
        }
        __syncthreads();
        if (tid < 128) {
            float v = red2[tid];   // tid = nn*16 + w
#pragma unroll
            for (int off = 1; off < 16; off <<= 1)
                v += __shfl_xor_sync(0xffffffffu, v, off);
            if ((tid & 15) == 0)
                out[bi * 4 * NA + 3 * NA + n0 + (tid >> 4)] = v;
        }
        return;
    }

    // ================= pair-MLP GEMM blocks ===============================
    const uint32_t sbase = smem_u32(smem);
    const int wid = tid >> 5;
    const int lane = tid & 31;

    const int rg = wid / 6;
    const int r6 = wid % 6;
    const int side = r6 / 3;
    const int hh = r6 % 3;
    const int mbase = rg * 32;
    const int jt0 = (hh == 0) ? 0 : (1 + 4 * hh);   // 0, 5, 9
    const int NTv = (hh == 0) ? 5 : 4;
    const int g = lane >> 2;
    const int tq = lane & 3;
    const int c0 = tq * 2;
    const int blane = lane & 15;

    if (tid < 128) {
        *(float*)(smem + SM_B2 + tid * 4) = (tid < H2) ? b2[tid] : 0.f;
        *(float*)(smem + SM_W3 + tid * 4) = (tid < H2) ? W3m[tid] : 0.f;
    }
    {   // W image -> smem (63232 B = 3952 uint4)
        uint4* dst = (uint4*)(smem + SM_W);
        const uint4* src = (const uint4*)g_Wimg;
        for (int i = tid; i < 3952; i += 768) dst[i] = src[i];
    }

    const float b3 = b3p[0];
    const float* b2s = (const float*)(smem + SM_B2);
    const float* W3s = (const float*)(smem + SM_W3);
    float* vp = (float*)(smem + SM_VP);

    const int srowB = 32 + side * 8 + g;
    const int sa_row0 = side * 16 + rg * 4;

    uint4 pf0, pf1;
    {
        int t0 = blockIdx.x;
        int bi = t0 >> 9, rem = t0 & 511;
        int a0 = (rem >> 5) << 4, b0 = (rem & 31) << 3;
        pf0 = stage_ld(tid, bi, a0, b0);
        pf1 = stage_ld(tid + 768, bi, a0, b0);
    }
    __syncthreads();

#pragma unroll 1
    for (int t = blockIdx.x; t < 1024; t += 148) {
        const int bi = t >> 9;
        const int rem = t & 511;
        const int a0 = (rem >> 5) << 4;
        const int b0 = (rem & 31) << 3;

        {
            int row0 = tid / 41, i0 = tid % 41;
            *(uint4*)(smem + SM_S + row0 * 656 + i0 * 16) = pf0;
            int idx1 = tid + 768;
            int row1 = idx1 / 41, i1 = idx1 % 41;
            *(uint4*)(smem + SM_S + row1 * 656 + i1 * 16) = pf1;
            int idx2 = tid + 1536;
            if (idx2 < 1968) {
                uint4 v = stage_ld(idx2, bi, a0, b0);
                int row2 = idx2 / 41, i2 = idx2 % 41;
                *(uint4*)(smem + SM_S + row2 * 656 + i2 * 16) = v;
            }
        }
        __syncthreads();

        float acc[2][5][4];
#pragma unroll
        for (int mt = 0; mt < 2; ++mt)
#pragma unroll
            for (int n = 0; n < 5; ++n)
#pragma unroll
                for (int q = 0; q < 4; ++q) acc[mt][n][q] = 0.f;

        const __half2* S2 = (const __half2*)(smem + SM_S);
        if (hh == 0)
            k2_mainloop<5>(acc, S2, sbase, srowB, sa_row0, jt0, blane, c0);
        else
            k2_mainloop<4>(acc, S2, sbase, srowB, sa_row0, jt0, blane, c0);

        if (t + 148 < 1024) {
            int tn = t + 148;
            int bin = tn >> 9, remn = tn & 511;
            int a0n = (remn >> 5) << 4, b0n = (remn & 31) << 3;
            pf0 = stage_ld(tid, bin, a0n, b0n);
            pf1 = stage_ld(tid + 768, bin, a0n, b0n);
        }

        float vs[2][2];
#pragma unroll
        for (int mt = 0; mt < 2; ++mt) {
            float s0 = 0.f, s1 = 0.f;
#pragma unroll
            for (int nt = 0; nt < 5; ++nt) {
                if (nt < NTv) {
                    int j = (jt0 + nt) * 8 + c0;
                    float w0 = W3s[j], w1 = W3s[j + 1];
                    float bb0 = b2s[j], bb1 = b2s[j + 1];
                    s0 += fmaxf(acc[mt][nt][0] + bb0, 0.f) * w0 + fmaxf(acc[mt][nt][1] + bb1, 0.f) * w1;
                    s1 += fmaxf(acc[mt][nt][2] + bb0, 0.f) * w0 + fmaxf(acc[mt][nt][3] + bb1, 0.f) * w1;
                }
            }
            s0 += __shfl_xor_sync(0xffffffffu, s0, 1);
            s0 += __shfl_xor_sync(0xffffffffu, s0, 2);
            s1 += __shfl_xor_sync(0xffffffffu, s1, 1);
            s1 += __shfl_xor_sync(0xffffffffu, s1, 2);
            vs[mt][0] = s0; vs[mt][1] = s1;
        }
        if (tq == 0) {
#pragma unroll
            for (int mt = 0; mt < 2; ++mt)
#pragma unroll
                for (int hf = 0; hf < 2; ++hf)
                    vp[hh * 256 + side * 128 + mbase + mt * 16 + hf * 8 + g] = vs[mt][hf];
        }
        __syncthreads();
        if (tid < 128) {
            float v1 = vp[tid] + vp[256 + tid] + vp[512 + tid];
            float v2 = vp[128 + tid] + vp[384 + tid] + vp[640 + tid];
            float s = 0.5f * (v1 + v2) + b3;
            float sp = fmaxf(s, 0.f) + log1pf(expf(-fabsf(s)));
            g_R2[(bi * NA + a0 + (tid >> 3)) * NB + b0 + (tid & 7)] = sp * sp;
        }
    }
}

// =========================================================================
// K4: flow only (needs all R2). 64 blocks, 8 anchors per block, 512 thr.
// =========================================================================
__global__ void __launch_bounds__(512) k4_flow(const float* __restrict__ anch,
                                               const float* __restrict__ actp,
                                               float* __restrict__ out) {
    int t = threadIdx.x;
    int bl = blockIdx.x;             // 0..63
    int bi = bl >> 5;
    int sub = t >> 6;                // 0..7
    int tt = t & 63;
    int a = (bl & 31) * 8 + sub;
    __shared__ float sx[512], sy[512], sz[512];
    const float* geo = g_geo + bi * 16;
    float q0 = geo[9], q1 = geo[10], q2 = geo[11];
    const float* ap = anch + bi * 3 * NB;
    const float* r2row = g_R2 + (bi * NA + a) * NB;
    float s0 = 0.f, s1 = 0.f, s2 = 0.f;
    for (int b = tt; b < NB; b += 64) {
        float r2 = r2row[b];
        s0 += 2.f * (ap[b] - q0) * r2;
        s1 += 2.f * (ap[NB + b] - q1) * r2;
        s2 += 2.f * (ap[2 * NB + b] - q2) * r2;
    }
    int base = sub * 64;
    sx[base + tt] = s0; sy[base + tt] = s1; sz[base + tt] = s2;
    __syncthreads();
    for (int s = 32; s; s >>= 1) {
        if (tt < s) {
            sx[base + tt] += sx[base + tt + s];
            sy[base + tt] += sy[base + tt + s];
            sz[base + tt] += sz[base + tt + s];
        }
        __syncthreads();
    }
    if (tt == 0) {
        float r0 = geo[6] - sx[base], r1 = geo[7] - sy[base], r2_ = geo[8] - sz[base];
        float p0 = geo[0] * r0 + geo[1] * r1 + geo[2] * r2_;
        float p1 = geo[1] * r0 + geo[3] * r1 + geo[4] * r2_;
        float p2 = geo[2] * r0 + geo[4] * r1 + geo[5] * r2_;
        const float* app = actp + bi * 3 * NA;
        out[bi * 4 * NA + 0 * NA + a] = p0 - app[a];
        out[bi * 4 * NA + 1 * NA + a] = p1 - app[NA + a];
        out[bi * 4 * NA + 2 * NA + a] = p2 - app[2 * NA + a];
    }
}

// =========================================================================
extern "C" void kernel_launch(void* const* d_in, const int* in_sizes, int n_in,
                              void* d_out, int out_size) {
    const float* actE  = (const float*)d_in[0];
    const float* anchE = (const float*)d_in[1];
    const float* actP  = (const float*)d_in[2];
    const float* anchP = (const float*)d_in[3];
    const float* W1    = (const float*)d_in[4];
    const float* b1    = (const float*)d_in[5];
    const float* W2    = (const float*)d_in[6];
    const float* b2    = (const float*)d_in[7];
    const float* W3    = (const float*)d_in[8];
    const float* b3    = (const float*)d_in[9];
    const float* pnW0  = (const float*)d_in[10];
    const float* pnb0  = (const float*)d_in[11];
    const float* pnW1  = (const float*)d_in[12];
    const float* pnb1  = (const float*)d_in[13];
    const float* pnW2  = (const float*)d_in[14];
    const float* pnb2  = (const float*)d_in[15];
    const float* pnW3  = (const float*)d_in[16];
    const float* pnb3  = (const float*)d_in[17];
    const float* pnW4  = (const float*)d_in[18];
    const float* pnb4  = (const float*)d_in[19];
    const float* headW = (const float*)d_in[20];
    float* out = (float*)d_out;

    cudaFuncSetAttribute(k2_hmma, cudaFuncAttributeMaxDynamicSharedMemorySize, SM_TOTAL);

    kp_prep<<<160, 256>>>(W2, actE, pnW0, pnb0, anchP);
    k1_h<<<dim3(5, 4, 8), dim3(16, 16)>>>(actE, anchE, W1, b1);
    k2_hmma<<<212, 768, SM_TOTAL>>>(b2, W3, b3,
                                    pnW1, pnb1, pnW2, pnb2, pnW3, pnb3,
                                    pnW4, pnb4, headW, out);
    k4_flow<<<64, 512>>>(anchP, actP, out);
}